// round 1
// baseline (speedup 1.0000x reference)
#include <cuda_runtime.h>
#include <math.h>

// Problem constants (shapes fixed by the reference)
#define NN_MAX 50000
#define EE_MAX 800000
#define IN_F   256
#define OUT_F  128
#define NHEAD  4
#define DHEAD  32

// ---------------- device scratch (static, no allocation) ----------------
__device__ float g_Wt[IN_F * OUT_F];                 // W transposed [k][o]
__device__ float g_Wx[(size_t)NN_MAX * OUT_F];       // x @ W.T
__device__ float g_ssrc[NN_MAX * NHEAD];
__device__ float g_sdst[NN_MAX * NHEAD];
__device__ float g_eexp[(size_t)EE_MAX * NHEAD];
__device__ float g_denom[NN_MAX * NHEAD];

// ---------------- K0: transpose W[o][k] -> g_Wt[k][o] ----------------
__global__ void k_transpose(const float* __restrict__ W) {
    int i = blockIdx.x * 256 + threadIdx.x;
    if (i < IN_F * OUT_F) {
        int o = i / IN_F;
        int k = i % IN_F;
        g_Wt[k * OUT_F + o] = W[i];
    }
}

// ---------------- K1: GEMM  Wx[n][o] = sum_k x[n][k] * W[o][k] ----------------
// Block: 256 threads, 32 nodes x 128 outs, 4x4 register tile per thread.
// smem: Wt_s[256][128] (128KB) + x_s[32][256] (32KB) = 160KB dynamic.
__global__ void k_gemm(const float* __restrict__ x, int Nn) {
    extern __shared__ float sm[];
    float* Wt_s = sm;                 // IN_F*OUT_F floats
    float* x_s  = sm + IN_F * OUT_F;  // 32*IN_F floats

    int tid = threadIdx.x;

    // Load Wt into smem (coalesced global, contiguous smem -> conflict free)
    {
        const float4* src = (const float4*)g_Wt;
        float4* dst = (float4*)Wt_s;
        #pragma unroll
        for (int i = tid; i < IN_F * OUT_F / 4; i += 256) dst[i] = src[i];
    }

    // Load 32 x-rows
    int n0 = blockIdx.x * 32;
    {
        float4* dst = (float4*)x_s;
        const float4* src = (const float4*)x;
        for (int i = tid; i < 32 * IN_F / 4; i += 256) {
            int row = i >> 6;           // IN_F/4 = 64 float4 per row
            int col = i & 63;
            int gr = n0 + row;
            dst[i] = (gr < Nn) ? src[(size_t)gr * 64 + col] : make_float4(0.f, 0.f, 0.f, 0.f);
        }
    }
    __syncthreads();

    float acc[4][4];
    #pragma unroll
    for (int j = 0; j < 4; j++)
        #pragma unroll
        for (int i = 0; i < 4; i++) acc[j][i] = 0.f;

    int o0 = (tid & 31) << 2;   // lanes vary over outs -> contiguous float4 smem reads
    int nb = (tid >> 5) << 2;   // warp-uniform node group -> broadcast smem reads

    #pragma unroll 4
    for (int k = 0; k < IN_F; k++) {
        float4 w = *(const float4*)(Wt_s + k * OUT_F + o0);
        #pragma unroll
        for (int j = 0; j < 4; j++) {
            float xv = x_s[(nb + j) * IN_F + k];
            acc[j][0] += xv * w.x;
            acc[j][1] += xv * w.y;
            acc[j][2] += xv * w.z;
            acc[j][3] += xv * w.w;
        }
    }

    #pragma unroll
    for (int j = 0; j < 4; j++) {
        int gr = n0 + nb + j;
        if (gr < Nn) {
            *(float4*)(g_Wx + (size_t)gr * OUT_F + o0) =
                make_float4(acc[j][0], acc[j][1], acc[j][2], acc[j][3]);
        }
    }
}

// ---------------- K2: per-node attention scores ----------------
// warp per node: s_src[n][h] = dot(Wx[n][h*32..], a_w[0:32]), s_dst with a_w[32:64]
__global__ void k_scores(const float* __restrict__ a_w, int Nn) {
    int gwarp = (blockIdx.x * blockDim.x + threadIdx.x) >> 5;
    int lane = threadIdx.x & 31;
    if (gwarp >= Nn) return;
    float as = a_w[lane];
    float ad = a_w[DHEAD + lane];
    const float* row = g_Wx + (size_t)gwarp * OUT_F;
    #pragma unroll
    for (int h = 0; h < NHEAD; h++) {
        float w = row[h * DHEAD + lane];
        float v1 = w * as;
        float v2 = w * ad;
        #pragma unroll
        for (int off = 16; off; off >>= 1) {
            v1 += __shfl_xor_sync(0xffffffffu, v1, off);
            v2 += __shfl_xor_sync(0xffffffffu, v2, off);
        }
        if (lane == 0) {
            g_ssrc[gwarp * NHEAD + h] = v1;
            g_sdst[gwarp * NHEAD + h] = v2;
        }
    }
}

// ---------------- K3: zero denom ----------------
__global__ void k_zero_denom(int n) {
    int i = blockIdx.x * 256 + threadIdx.x;
    if (i < n) g_denom[i] = 0.f;
}

__device__ __forceinline__ float lrelu02(float v) {
    return v > 0.f ? v : 0.2f * v;
}

// ---------------- K4: edge exp scores + denom segment-sum ----------------
__global__ void k_edge(const int* __restrict__ ei, int Ee) {
    int e = blockIdx.x * 256 + threadIdx.x;
    if (e >= Ee) return;
    int s = ei[e];
    int d = ei[Ee + e];
    float4 ss = *(const float4*)(g_ssrc + s * 4);
    float4 sd = *(const float4*)(g_sdst + d * 4);
    float4 v;
    v.x = expf(lrelu02(ss.x + sd.x));
    v.y = expf(lrelu02(ss.y + sd.y));
    v.z = expf(lrelu02(ss.z + sd.z));
    v.w = expf(lrelu02(ss.w + sd.w));
    *(float4*)(g_eexp + (size_t)e * 4) = v;
    asm volatile("red.global.add.v4.f32 [%0], {%1,%2,%3,%4};"
                 :: "l"(g_denom + d * 4), "f"(v.x), "f"(v.y), "f"(v.z), "f"(v.w)
                 : "memory");
}

// ---------------- K5: weighted aggregation (warp per edge) ----------------
__global__ void k_agg(const int* __restrict__ ei, float* __restrict__ out, int Ee) {
    int e = (blockIdx.x * blockDim.x + threadIdx.x) >> 5;
    if (e >= Ee) return;
    int lane = threadIdx.x & 31;
    int s = ei[e];
    int d = ei[Ee + e];
    int h = lane >> 3;  // lane*4 spans columns [lane*4, lane*4+4) -> head = lane/8
    float alpha = g_eexp[(size_t)e * 4 + h] / (g_denom[d * 4 + h] + 1e-8f);
    float4 w = *(const float4*)(g_Wx + (size_t)s * OUT_F + lane * 4);
    float* dst = out + (size_t)d * OUT_F + lane * 4;
    asm volatile("red.global.add.v4.f32 [%0], {%1,%2,%3,%4};"
                 :: "l"(dst), "f"(w.x * alpha), "f"(w.y * alpha), "f"(w.z * alpha), "f"(w.w * alpha)
                 : "memory");
}

// ---------------- K6: ELU epilogue in place ----------------
__global__ void k_elu(float* __restrict__ out, int n4) {
    int i = blockIdx.x * 256 + threadIdx.x;
    if (i >= n4) return;
    float4 v = ((float4*)out)[i];
    v.x = v.x > 0.f ? v.x : expm1f(v.x);
    v.y = v.y > 0.f ? v.y : expm1f(v.y);
    v.z = v.z > 0.f ? v.z : expm1f(v.z);
    v.w = v.w > 0.f ? v.w : expm1f(v.w);
    ((float4*)out)[i] = v;
}

// ---------------- launch ----------------
extern "C" void kernel_launch(void* const* d_in, const int* in_sizes, int n_in,
                              void* d_out, int out_size) {
    const float* x   = (const float*)d_in[0];
    const int*   ei  = (const int*)d_in[1];
    const float* W   = (const float*)d_in[2];
    const float* a_w = (const float*)d_in[3];
    float* out = (float*)d_out;

    int Nn = in_sizes[0] / IN_F;
    int Ee = in_sizes[1] / 2;

    const int smem_gemm = (IN_F * OUT_F + 32 * IN_F) * sizeof(float);  // 163840
    cudaFuncSetAttribute(k_gemm, cudaFuncAttributeMaxDynamicSharedMemorySize, smem_gemm);

    cudaMemsetAsync(d_out, 0, (size_t)Nn * OUT_F * sizeof(float));

    k_transpose<<<(IN_F * OUT_F + 255) / 256, 256>>>(W);
    k_gemm<<<(Nn + 31) / 32, 256, smem_gemm>>>(x, Nn);
    k_scores<<<(Nn + 7) / 8, 256>>>(a_w, Nn);
    k_zero_denom<<<(Nn * NHEAD + 255) / 256, 256>>>(Nn * NHEAD);
    k_edge<<<(Ee + 255) / 256, 256>>>(ei, Ee);
    k_agg<<<(Ee + 7) / 8, 256>>>(ei, out, Ee);
    k_elu<<<(Nn * OUT_F / 4 + 255) / 256, 256>>>(out, Nn * OUT_F / 4);
}

// round 2
// speedup vs baseline: 1.3119x; 1.3119x over previous
#include <cuda_runtime.h>
#include <math.h>

#define NN_MAX 50000
#define EE_MAX 800000
#define IN_F   256
#define OUT_F  128
#define NHEAD  4
#define DHEAD  32

// ---------------- device scratch (static, no allocation) ----------------
__device__ float g_Wt[IN_F * OUT_F];                 // W transposed [k][o]
__device__ float g_Wx[(size_t)NN_MAX * OUT_F];       // x @ W.T
__device__ float g_ssrc[NN_MAX * NHEAD];
__device__ float g_sdst[NN_MAX * NHEAD];
__device__ float g_eexp[(size_t)EE_MAX * NHEAD];
__device__ float g_denom[NN_MAX * NHEAD];

// ---------------- f32x2 packed math helpers (sm_103a FFMA2) ----------------
__device__ __forceinline__ unsigned long long pack_dup(float v) {
    unsigned long long r;
    asm("mov.b64 %0, {%1, %1};" : "=l"(r) : "f"(v));
    return r;
}
__device__ __forceinline__ unsigned long long fma2(unsigned long long a,
                                                   unsigned long long b,
                                                   unsigned long long c) {
    unsigned long long d;
    asm("fma.rn.f32x2 %0, %1, %2, %3;" : "=l"(d) : "l"(a), "l"(b), "l"(c));
    return d;
}
__device__ __forceinline__ void unpack2(unsigned long long p, float& lo, float& hi) {
    asm("mov.b64 {%0, %1}, %2;" : "=f"(lo), "=f"(hi) : "l"(p));
}

// ---------------- K0: prep — transpose W + zero denom ----------------
__global__ void k_prep(const float* __restrict__ W, int Nn) {
    int i = blockIdx.x * 256 + threadIdx.x;
    if (i < IN_F * OUT_F) {
        int o = i / IN_F;
        int k = i % IN_F;
        g_Wt[k * OUT_F + o] = W[i];
    }
    if (i < Nn * NHEAD) g_denom[i] = 0.f;
}

// ---------------- K1: GEMM (f32x2) + fused attention scores ----------------
// 256 threads, 64 rows x 128 cols per block. Each warp: 8 rows, lanes over cols.
// Per thread: 8 rows x 4 cols, accumulated as 8x2 f32x2 pairs.
// smem: Wt_s[256][128] (128KB) + x_s[64][256] (64KB) = 192KB.
__global__ void __launch_bounds__(256, 1)
k_gemm(const float* __restrict__ x, const float* __restrict__ a_w, int Nn) {
    extern __shared__ float sm[];
    float* Wt_s = sm;                 // IN_F*OUT_F
    float* x_s  = sm + IN_F * OUT_F;  // 64*IN_F

    int tid  = threadIdx.x;
    int lane = tid & 31;
    int wid  = tid >> 5;
    int n0   = blockIdx.x * 64;

    // Fill W smem (coalesced float4)
    {
        const float4* src = (const float4*)g_Wt;
        float4* dst = (float4*)Wt_s;
        #pragma unroll
        for (int i = tid; i < IN_F * OUT_F / 4; i += 256) dst[i] = src[i];
    }
    // Fill x smem (64 rows, guarded)
    {
        float4* dst = (float4*)x_s;
        const float4* src = (const float4*)x;
        #pragma unroll
        for (int i = tid; i < 64 * IN_F / 4; i += 256) {
            int row = i >> 6;            // IN_F/4 = 64 float4 per row
            int col = i & 63;
            int gr = n0 + row;
            dst[i] = (gr < Nn) ? src[(size_t)gr * 64 + col]
                               : make_float4(0.f, 0.f, 0.f, 0.f);
        }
    }
    __syncthreads();

    unsigned long long acc[8][2];
    #pragma unroll
    for (int r = 0; r < 8; r++) { acc[r][0] = 0ull; acc[r][1] = 0ull; }

    int o0 = lane << 2;                       // col base (float4 aligned)
    const float* xrow = x_s + (wid * 8) * IN_F;

    #pragma unroll 4
    for (int k = 0; k < IN_F; k++) {
        ulonglong2 w2 = *(const ulonglong2*)(Wt_s + k * OUT_F + o0);
        #pragma unroll
        for (int r = 0; r < 8; r++) {
            unsigned long long xp = pack_dup(xrow[r * IN_F + k]);
            acc[r][0] = fma2(xp, w2.x, acc[r][0]);
            acc[r][1] = fma2(xp, w2.y, acc[r][1]);
        }
    }

    // Epilogue: write Wx + fused scores
    float4 as4 = *(const float4*)(a_w + (lane & 7) * 4);
    float4 ad4 = *(const float4*)(a_w + DHEAD + (lane & 7) * 4);
    int h = lane >> 3;

    #pragma unroll
    for (int r = 0; r < 8; r++) {
        int gr = n0 + wid * 8 + r;            // warp-uniform validity
        if (gr < Nn) {
            float f0, f1, f2, f3;
            unpack2(acc[r][0], f0, f1);
            unpack2(acc[r][1], f2, f3);
            *(float4*)(g_Wx + (size_t)gr * OUT_F + o0) = make_float4(f0, f1, f2, f3);
            float p1 = f0 * as4.x + f1 * as4.y + f2 * as4.z + f3 * as4.w;
            float p2 = f0 * ad4.x + f1 * ad4.y + f2 * ad4.z + f3 * ad4.w;
            #pragma unroll
            for (int off = 4; off; off >>= 1) {
                p1 += __shfl_xor_sync(0xffffffffu, p1, off);
                p2 += __shfl_xor_sync(0xffffffffu, p2, off);
            }
            if ((lane & 7) == 0) {
                g_ssrc[gr * NHEAD + h] = p1;
                g_sdst[gr * NHEAD + h] = p2;
            }
        }
    }
}

__device__ __forceinline__ float lrelu02(float v) {
    return v > 0.f ? v : 0.2f * v;
}

// ---------------- K2: edge exp scores + denom segment-sum ----------------
__global__ void k_edge(const int* __restrict__ ei, int Ee) {
    int e = blockIdx.x * 256 + threadIdx.x;
    if (e >= Ee) return;
    int s = ei[e];
    int d = ei[Ee + e];
    float4 ss = *(const float4*)(g_ssrc + s * 4);
    float4 sd = *(const float4*)(g_sdst + d * 4);
    float4 v;
    v.x = __expf(lrelu02(ss.x + sd.x));
    v.y = __expf(lrelu02(ss.y + sd.y));
    v.z = __expf(lrelu02(ss.z + sd.z));
    v.w = __expf(lrelu02(ss.w + sd.w));
    *(float4*)(g_eexp + (size_t)e * 4) = v;
    asm volatile("red.global.add.v4.f32 [%0], {%1,%2,%3,%4};"
                 :: "l"(g_denom + d * 4), "f"(v.x), "f"(v.y), "f"(v.z), "f"(v.w)
                 : "memory");
}

// ---------------- K3: weighted aggregation (warp per edge) ----------------
__global__ void k_agg(const int* __restrict__ ei, float* __restrict__ out, int Ee) {
    int e = (blockIdx.x * blockDim.x + threadIdx.x) >> 5;
    if (e >= Ee) return;
    int lane = threadIdx.x & 31;
    int s = ei[e];
    int d = ei[Ee + e];
    int h = lane >> 3;
    float alpha = g_eexp[(size_t)e * 4 + h] / (g_denom[d * 4 + h] + 1e-8f);
    float4 w = *(const float4*)(g_Wx + (size_t)s * OUT_F + lane * 4);
    float* dst = out + (size_t)d * OUT_F + lane * 4;
    asm volatile("red.global.add.v4.f32 [%0], {%1,%2,%3,%4};"
                 :: "l"(dst), "f"(w.x * alpha), "f"(w.y * alpha), "f"(w.z * alpha), "f"(w.w * alpha)
                 : "memory");
}

// ---------------- K4: ELU epilogue in place ----------------
__global__ void k_elu(float* __restrict__ out, int n4) {
    int i = blockIdx.x * 256 + threadIdx.x;
    if (i >= n4) return;
    float4 v = ((float4*)out)[i];
    v.x = v.x > 0.f ? v.x : expm1f(v.x);
    v.y = v.y > 0.f ? v.y : expm1f(v.y);
    v.z = v.z > 0.f ? v.z : expm1f(v.z);
    v.w = v.w > 0.f ? v.w : expm1f(v.w);
    ((float4*)out)[i] = v;
}

// ---------------- launch ----------------
extern "C" void kernel_launch(void* const* d_in, const int* in_sizes, int n_in,
                              void* d_out, int out_size) {
    const float* x   = (const float*)d_in[0];
    const int*   ei  = (const int*)d_in[1];
    const float* W   = (const float*)d_in[2];
    const float* a_w = (const float*)d_in[3];
    float* out = (float*)d_out;

    int Nn = in_sizes[0] / IN_F;
    int Ee = in_sizes[1] / 2;

    const int smem_gemm = (IN_F * OUT_F + 64 * IN_F) * sizeof(float);  // 196608
    cudaFuncSetAttribute(k_gemm, cudaFuncAttributeMaxDynamicSharedMemorySize, smem_gemm);

    cudaMemsetAsync(d_out, 0, (size_t)Nn * OUT_F * sizeof(float));

    int prep_n = (Nn * NHEAD > IN_F * OUT_F) ? Nn * NHEAD : IN_F * OUT_F;
    k_prep<<<(prep_n + 255) / 256, 256>>>(W, Nn);
    k_gemm<<<(Nn + 63) / 64, 256, smem_gemm>>>(x, a_w, Nn);
    k_edge<<<(Ee + 255) / 256, 256>>>(ei, Ee);
    k_agg<<<(Ee + 7) / 8, 256>>>(ei, out, Ee);
    k_elu<<<(Nn * OUT_F / 4 + 255) / 256, 256>>>(out, Nn * OUT_F / 4);
}